// round 1
// baseline (speedup 1.0000x reference)
#include <cuda_runtime.h>
#include <math.h>

#define BB 32
#define HH 512
#define WW 512
#define TH 16               // output rows per block
#define NTHREADS 256
#define TILE_ROWS (TH + 4)  // with 2-row halo each side
#define SW 520              // smem pitch for uint8 target tile (516 used)

// ---- device-global accumulators (no allocations allowed) ----
__device__ float g_acc[3];        // [0]=ce_sum, [1]=valid_count, [2]=focal_sum
__device__ float g_inter[BB];
__device__ float g_bp[BB];
__device__ float g_bt[BB];
__device__ unsigned int g_flag;   // OR of "high words" -> 0 means target is int64

__global__ void be_zero_kernel() {
    int i = threadIdx.x;
    if (i < 3)  g_acc[i] = 0.f;
    if (i < BB) { g_inter[i] = 0.f; g_bp[i] = 0.f; g_bt[i] = 0.f; }
    if (i == 63) g_flag = 0u;
}

// Detect int64 vs int32 target: interpret the first 4096 32-bit words as
// (lo,hi) pairs. If every "hi" word is zero -> int64 (values 0/1, non-negative).
// For int32 random 0/1 data the odd words are the random values themselves,
// so the OR is nonzero with overwhelming probability.
__global__ void be_detect_kernel(const unsigned int* __restrict__ t) {
    unsigned int v = 0;
    for (int i = threadIdx.x; i < 2048; i += blockDim.x)
        v |= t[2 * i + 1];
    #pragma unroll
    for (int o = 16; o > 0; o >>= 1)
        v |= __shfl_down_sync(0xffffffffu, v, o);
    if ((threadIdx.x & 31) == 0 && v) atomicOr(&g_flag, v);
}

__device__ __forceinline__ float warp_red_sum(float v) {
    #pragma unroll
    for (int o = 16; o > 0; o >>= 1)
        v += __shfl_down_sync(0xffffffffu, v, o);
    return v;
}

__global__ __launch_bounds__(NTHREADS)
void be_main_kernel(const float* __restrict__ pred, const void* __restrict__ target) {
    __shared__ unsigned char  st[TILE_ROWS * SW];      // target tile (with halo), zero-padded
    __shared__ unsigned short hs[TILE_ROWS * WW];      // horizontal 5-sums
    __shared__ float          red[8][6];

    const int b   = blockIdx.y;          // image index
    const int ry0 = blockIdx.x * TH;     // first output row of this stripe
    const int tid = threadIdx.x;

    const bool is64 = (g_flag == 0u);
    const long long imgBase = (long long)b * (HH * WW);
    const long long* __restrict__ t64 = (const long long*)target;
    const int*       __restrict__ t32 = (const int*)target;

    // ---- load target tile (rows ry0-2 .. ry0+TH+1, cols -2 .. 513), zero pad ----
    for (int idx = tid; idx < TILE_ROWS * 516; idx += NTHREADS) {
        int j  = idx / 516;
        int i  = idx - j * 516;
        int gr = ry0 - 2 + j;
        int gc = i - 2;
        int v = 0;
        if (gr >= 0 && gr < HH && gc >= 0 && gc < WW) {
            long long gi = imgBase + (long long)gr * WW + gc;
            v = is64 ? (int)t64[gi] : t32[gi];
        }
        st[j * SW + i] = (unsigned char)v;
    }
    __syncthreads();

    // ---- horizontal 5-sum: hs[j][c] = sum of st[j][c..c+4] (global cols c-2..c+2) ----
    for (int idx = tid; idx < TILE_ROWS * WW; idx += NTHREADS) {
        int j = idx >> 9;
        int c = idx & (WW - 1);
        const unsigned char* r = st + j * SW + c;
        hs[idx] = (unsigned short)((int)r[0] + r[1] + r[2] + r[3] + r[4]);
    }
    __syncthreads();

    // ---- main per-pixel pass ----
    float a_ce = 0.f, a_valid = 0.f, a_focal = 0.f;
    float a_inter = 0.f, a_bp = 0.f, a_bt = 0.f;

    const float* __restrict__ p0base = pred + (long long)b * 2 * HH * WW + (long long)ry0 * WW;
    const float* __restrict__ p1base = p0base + HH * WW;

    #pragma unroll 4
    for (int k = 0; k < (TH * WW) / NTHREADS; k++) {
        int idx = tid + k * NTHREADS;
        int rr  = idx >> 9;          // local row 0..TH-1
        int c   = idx & (WW - 1);
        int off = rr * WW + c;

        float p0 = p0base[off];
        float p1 = p1base[off];
        int   t  = (int)st[(rr + 2) * SW + (c + 2)];

        // 5x5 box sum via 5 vertical adds of horizontal sums
        int s = (int)hs[rr * WW + c] + hs[(rr + 1) * WW + c] + hs[(rr + 2) * WW + c]
              + (int)hs[(rr + 3) * WW + c] + hs[(rr + 4) * WW + c];
        float bnd = (s > 0 && s <= 24) ? 1.f : 0.f;

        // two-class log-softmax via softplus of z = p1 - p0
        float z   = p1 - p0;
        float az  = fabsf(z);
        float e   = __expf(-az);
        float spS = __logf(1.f + e);     // softplus(-|z|) = -log p(argmax)
        float spL = az + spS;            // -log p(other)
        float rcp = __fdividef(1.f, 1.f + e);
        float pmax = rcp;                // prob of argmax class
        float pmin = e * rcp;            // prob of other class

        int  am1 = (z >= 0.f) ? 1 : 0;   // argmax class
        int  tc  = (t > 1) ? 1 : t;      // clamp (JAX take_along_axis clips OOB index)
        float ce = (tc == am1) ? spS : spL;
        float pt = (tc == am1) ? pmax : pmin;   // exp(-ce) = prob of true class
        float prob1 = am1 ? pmax : pmin;        // softmax class-1 prob

        float valid = (t != 250) ? 1.f : 0.f;
        a_ce    += ce * valid;
        a_valid += valid;
        float om = 1.f - pt;
        a_focal += 0.25f * om * om * ce;

        float tf = (float)t;
        float pb = prob1 * bnd;
        a_bp    += pb;
        a_bt    += tf * bnd;
        a_inter += pb * tf;
    }

    // ---- block reduction (6 values), then one atomic per accumulator ----
    float vals[6] = { a_ce, a_valid, a_focal, a_inter, a_bp, a_bt };
    int lane = tid & 31, w = tid >> 5;
    #pragma unroll
    for (int i = 0; i < 6; i++) {
        float r = warp_red_sum(vals[i]);
        if (lane == 0) red[w][i] = r;
    }
    __syncthreads();
    if (tid < 6) {
        float r = 0.f;
        #pragma unroll
        for (int wi = 0; wi < NTHREADS / 32; wi++) r += red[wi][tid];
        if      (tid == 0) atomicAdd(&g_acc[0], r);
        else if (tid == 1) atomicAdd(&g_acc[1], r);
        else if (tid == 2) atomicAdd(&g_acc[2], r);
        else if (tid == 3) atomicAdd(&g_inter[b], r);
        else if (tid == 4) atomicAdd(&g_bp[b], r);
        else               atomicAdd(&g_bt[b], r);
    }
}

__global__ void be_final_kernel(float* __restrict__ out) {
    int b = threadIdx.x;  // 32 threads
    float dice = 2.f * g_inter[b] / (g_bp[b] + g_bt[b] + 1e-8f);
    dice = warp_red_sum(dice);
    if (b == 0) {
        float ce_loss = g_acc[0] / fmaxf(g_acc[1], 1.f);
        float focal   = g_acc[2] * (1.0f / (float)((long long)BB * HH * WW));
        float bdice   = 1.f - dice * (1.0f / (float)BB);
        out[0] = ce_loss + focal + bdice;
    }
}

extern "C" void kernel_launch(void* const* d_in, const int* in_sizes, int n_in,
                              void* d_out, int out_size) {
    // Identify pred vs target robustly by element count.
    const void* pred = d_in[0];
    const void* targ = d_in[1];
    if (n_in >= 2 && in_sizes[0] == BB * HH * WW && in_sizes[1] == BB * 2 * HH * WW) {
        pred = d_in[1];
        targ = d_in[0];
    }

    be_zero_kernel<<<1, 64>>>();
    be_detect_kernel<<<1, 256>>>((const unsigned int*)targ);
    dim3 grid(HH / TH, BB);
    be_main_kernel<<<grid, NTHREADS>>>((const float*)pred, targ);
    be_final_kernel<<<1, 32>>>((float*)d_out);
}

// round 2
// speedup vs baseline: 1.0314x; 1.0314x over previous
#include <cuda_runtime.h>
#include <math.h>

#define BB 32
#define HH 512
#define WW 512
#define TH 16                    // output rows per block
#define NTHREADS 256
#define NSTRIPES (HH / TH)       // 32
#define NBLK (BB * NSTRIPES)     // 1024
#define TILE_ROWS (TH + 4)       // 2-row halo each side
#define SW 520                   // smem pitch for uint8 target tile (516 used)

// ---- per-block partials (every slot written every call -> no zeroing kernel) ----
__device__ float g_ce[NBLK], g_valid[NBLK], g_focal[NBLK];
__device__ float g_it[NBLK], g_bp[NBLK], g_bt[NBLK];

__device__ __forceinline__ float warp_red_sum(float v) {
    #pragma unroll
    for (int o = 16; o > 0; o >>= 1)
        v += __shfl_down_sync(0xffffffffu, v, o);
    return v;
}

__global__ __launch_bounds__(NTHREADS)
void be_main(const float* __restrict__ pred, const void* __restrict__ target) {
    __shared__ unsigned char  st[TILE_ROWS * SW];   // target tile (halo, zero-padded)
    __shared__ unsigned short hs[TILE_ROWS * WW];   // horizontal 5-sums
    __shared__ float          red[8][6];

    const int b   = blockIdx.y;        // image
    const int sp  = blockIdx.x;        // stripe
    const int ry0 = sp * TH;
    const int tid = threadIdx.x;

    // ---- in-block dtype detection over first 16KB (valid for both dtypes).
    // int64 targets (values 0/1): every hi-word is 0. int32 targets: the odd
    // words are the random 0/1 values themselves -> OR nonzero w.h.p.
    unsigned int v = 0;
    const unsigned int* tw = (const unsigned int*)target;
    #pragma unroll
    for (int i = 0; i < 8; i++)
        v |= tw[2 * (tid + i * NTHREADS) + 1];
    const bool is64 = (__syncthreads_or((int)v) == 0);

    const long long imgBase = (long long)b * (HH * WW);
    const long long* __restrict__ t64 = (const long long*)target;
    const int*       __restrict__ t32 = (const int*)target;

    // ---- load target tile (rows ry0-2 .. ry0+TH+1, cols -2 .. 513), zero pad ----
    for (int idx = tid; idx < TILE_ROWS * 516; idx += NTHREADS) {
        int j  = idx / 516;
        int i  = idx - j * 516;
        int gr = ry0 - 2 + j;
        int gc = i - 2;
        int vv = 0;
        if (gr >= 0 && gr < HH && gc >= 0 && gc < WW) {
            long long gi = imgBase + (long long)gr * WW + gc;
            vv = is64 ? (int)t64[gi] : t32[gi];
        }
        st[j * SW + i] = (unsigned char)vv;
    }
    __syncthreads();

    // ---- horizontal 5-sum: hs[j][c] = sum st[j][c..c+4] (global cols c-2..c+2) ----
    for (int idx = tid; idx < TILE_ROWS * WW; idx += NTHREADS) {
        int j = idx >> 9;
        int c = idx & (WW - 1);
        const unsigned char* r = st + j * SW + c;
        hs[idx] = (unsigned short)((int)r[0] + r[1] + r[2] + r[3] + r[4]);
    }
    __syncthreads();

    // ---- main per-pixel pass: float4 over pred, 4 pixels per iter per thread ----
    float a_ce = 0.f, a_valid = 0.f, a_focal = 0.f;
    float a_it = 0.f, a_bp = 0.f, a_bt = 0.f;

    const float4* __restrict__ p0b =
        (const float4*)(pred + (long long)b * 2 * HH * WW + (long long)ry0 * WW);
    const float4* __restrict__ p1b =
        (const float4*)(pred + (long long)b * 2 * HH * WW + (long long)(HH + ry0) * WW);

    #pragma unroll
    for (int k = 0; k < (TH * WW / 4) / NTHREADS; k++) {
        int g  = tid + k * NTHREADS;
        float4 q0 = p0b[g];
        float4 q1 = p1b[g];
        int rr = g >> 7;             // (g*4) >> 9
        int c0 = (g << 2) & (WW - 1);

        #pragma unroll
        for (int u = 0; u < 4; u++) {
            int c = c0 + u;
            float p0 = (&q0.x)[u];
            float p1 = (&q1.x)[u];
            int   t  = (int)st[(rr + 2) * SW + (c + 2)];

            int s = (int)hs[rr * WW + c] + hs[(rr + 1) * WW + c] + hs[(rr + 2) * WW + c]
                  + (int)hs[(rr + 3) * WW + c] + hs[(rr + 4) * WW + c];
            float bnd = (s > 0 && s <= 24) ? 1.f : 0.f;

            // two-class log-softmax via softplus of z = p1 - p0
            float z   = p1 - p0;
            float az  = fabsf(z);
            float e   = __expf(-az);
            float spS = __logf(1.f + e);     // -log p(argmax)
            float spL = az + spS;            // -log p(other)
            float rcp = __fdividef(1.f, 1.f + e);
            float pmax = rcp;
            float pmin = e * rcp;

            int  am1 = (z >= 0.f) ? 1 : 0;
            int  tc  = (t > 1) ? 1 : t;      // JAX take_along_axis clamps OOB index
            float ce = (tc == am1) ? spS : spL;
            float pt = (tc == am1) ? pmax : pmin;
            float prob1 = am1 ? pmax : pmin;

            float valid = (t != 250) ? 1.f : 0.f;
            a_ce    += ce * valid;
            a_valid += valid;
            float om = 1.f - pt;
            a_focal += 0.25f * om * om * ce;

            float tf = (float)t;
            float pb = prob1 * bnd;
            a_bp += pb;
            a_bt += tf * bnd;
            a_it += pb * tf;
        }
    }

    // ---- block reduction (6 values), write per-block partials (no atomics) ----
    float vals[6] = { a_ce, a_valid, a_focal, a_it, a_bp, a_bt };
    int lane = tid & 31, w = tid >> 5;
    #pragma unroll
    for (int i = 0; i < 6; i++) {
        float r = warp_red_sum(vals[i]);
        if (lane == 0) red[w][i] = r;
    }
    __syncthreads();
    if (tid < 6) {
        float r = 0.f;
        #pragma unroll
        for (int wi = 0; wi < NTHREADS / 32; wi++) r += red[wi][tid];
        int p = b * NSTRIPES + sp;
        if      (tid == 0) g_ce[p]    = r;
        else if (tid == 1) g_valid[p] = r;
        else if (tid == 2) g_focal[p] = r;
        else if (tid == 3) g_it[p]    = r;
        else if (tid == 4) g_bp[p]    = r;
        else               g_bt[p]    = r;
    }
}

// 1024 threads; partial index p = b*32 + stripe, so warp w == image w.
__global__ __launch_bounds__(NBLK)
void be_final(float* __restrict__ out) {
    __shared__ float sdice[32], sce[32], sva[32], sfo[32];
    int tid = threadIdx.x, lane = tid & 31, w = tid >> 5;

    float it = g_it[tid], bp = g_bp[tid], bt = g_bt[tid];
    float ce = g_ce[tid], va = g_valid[tid], fo = g_focal[tid];

    it = warp_red_sum(it); bp = warp_red_sum(bp); bt = warp_red_sum(bt);
    ce = warp_red_sum(ce); va = warp_red_sum(va); fo = warp_red_sum(fo);

    if (lane == 0) {
        sdice[w] = 2.f * it / (bp + bt + 1e-8f);
        sce[w] = ce; sva[w] = va; sfo[w] = fo;
    }
    __syncthreads();
    if (w == 0) {
        float d = sdice[lane], c = sce[lane], vv = sva[lane], f = sfo[lane];
        d = warp_red_sum(d); c = warp_red_sum(c);
        vv = warp_red_sum(vv); f = warp_red_sum(f);
        if (lane == 0) {
            float ce_loss = c / fmaxf(vv, 1.f);
            float focal   = f * (1.0f / (float)(BB * HH * WW));
            float bdice   = 1.f - d * (1.0f / (float)BB);
            out[0] = ce_loss + focal + bdice;
        }
    }
}

extern "C" void kernel_launch(void* const* d_in, const int* in_sizes, int n_in,
                              void* d_out, int out_size) {
    const void* pred = d_in[0];
    const void* targ = d_in[1];
    if (n_in >= 2 && in_sizes[0] == BB * HH * WW && in_sizes[1] == BB * 2 * HH * WW) {
        pred = d_in[1];
        targ = d_in[0];
    }
    dim3 grid(NSTRIPES, BB);
    be_main<<<grid, NTHREADS>>>((const float*)pred, targ);
    be_final<<<1, NBLK>>>((float*)d_out);
}